// round 1
// baseline (speedup 1.0000x reference)
#include <cuda_runtime.h>

#define NN 100000
#define EE 1600000
#define TPB 256

// ---- scratch (no allocations allowed; __device__ globals) ----
__device__ float    g_xl[NN * 64];       // x @ Wl + bl   (source transform)
__device__ float    g_xr[NN * 64];       // x @ Wr + br   (target transform)
__device__ float4   g_alpha[EE];         // per-edge raw attention logits [E,4]
__device__ unsigned g_amaxkey[NN * 4];   // segment max as monotonic uint key
__device__ float    g_denom[NN * 4];     // segment softmax denominator
__device__ float    g_gatesum[NN];       // sum of edge gates per target
__device__ float    g_deg[NN];           // in-degree per target

// order-preserving float <-> uint mapping for atomicMax on floats
__device__ __forceinline__ unsigned f2key(float f) {
    unsigned u = __float_as_uint(f);
    return (u & 0x80000000u) ? ~u : (u | 0x80000000u);
}
__device__ __forceinline__ float key2f(unsigned k) {
    return __uint_as_float((k & 0x80000000u) ? (k ^ 0x80000000u) : ~k);
}
__device__ __forceinline__ float sigmoidf_(float v) {
    return 1.f / (1.f + __expf(-v));
}
__device__ __forceinline__ void red4(float* p, float a, float b, float c, float d) {
    asm volatile("red.global.add.v4.f32 [%0], {%1,%2,%3,%4};"
                 :: "l"(p), "f"(a), "f"(b), "f"(c), "f"(d) : "memory");
}

// ---------------------------------------------------------------------------
// Kernel 1: node transforms xl/xr + init all accumulators (incl. zeroing out)
// 4 nodes per 256-thread block; Wl/Wr staged in shared.
// ---------------------------------------------------------------------------
__global__ void k_prep(const float* __restrict__ x,
                       const float* __restrict__ Wl, const float* __restrict__ bl,
                       const float* __restrict__ Wr, const float* __restrict__ br,
                       float* __restrict__ out) {
    __shared__ float Wls[64 * 64];
    __shared__ float Wrs[64 * 64];
    __shared__ float xs[4 * 64];
    int t = threadIdx.x;
#pragma unroll
    for (int i = 0; i < 16; i++) {
        Wls[t + i * TPB] = Wl[t + i * TPB];
        Wrs[t + i * TPB] = Wr[t + i * TPB];
    }
    xs[t] = x[(size_t)blockIdx.x * TPB + t];
    __syncthreads();

    int nl = t >> 6, col = t & 63;
    int n = blockIdx.x * 4 + nl;
    float al = bl[col], ar = br[col];
#pragma unroll
    for (int k = 0; k < 64; k++) {
        float xv = xs[nl * 64 + k];
        al += xv * Wls[k * 64 + col];
        ar += xv * Wrs[k * 64 + col];
    }
    g_xl[(size_t)n * 64 + col] = al;
    g_xr[(size_t)n * 64 + col] = ar;
    out[(size_t)n * 64 + col]  = 0.f;       // accumulate GAT output directly in d_out
    if (col < 4) { g_amaxkey[n * 4 + col] = 0u; g_denom[n * 4 + col] = 0.f; }
    if (col == 4) g_gatesum[n] = 0.f;
    if (col == 5) g_deg[n] = 0.f;
}

// ---------------------------------------------------------------------------
// Kernel 2: per-edge gate MLP + attention logits + segment max / gate sums
// ---------------------------------------------------------------------------
__global__ void k_edge1(const int* __restrict__ ei, const float* __restrict__ eag,
                        const float* __restrict__ We, const float* __restrict__ att,
                        const float* __restrict__ Wg1, const float* __restrict__ bg1,
                        const float* __restrict__ Wg2, const float* __restrict__ bg2) {
    __shared__ float We_s[16 * 64];
    __shared__ float Wg1_s[16 * 32];
    __shared__ float Wg2_s[32];
    __shared__ float bg1_s[32];
    __shared__ float att_s[64];
    int t = threadIdx.x;
    for (int i = t; i < 1024; i += TPB) We_s[i] = We[i];
    for (int i = t; i < 512;  i += TPB) Wg1_s[i] = Wg1[i];
    if (t < 32) { Wg2_s[t] = Wg2[t]; bg1_s[t] = bg1[t]; }
    if (t < 64) att_s[t] = att[t];
    __syncthreads();

    int e = blockIdx.x * TPB + t;   // E % TPB == 0
    int src = ei[e];
    int tgt = ei[EE + e];

    float ea[16];
    const float4* eap = (const float4*)(eag + (size_t)e * 16);
#pragma unroll
    for (int i = 0; i < 4; i++) {
        float4 v = eap[i];
        ea[4 * i + 0] = v.x; ea[4 * i + 1] = v.y;
        ea[4 * i + 2] = v.z; ea[4 * i + 3] = v.w;
    }

    // gate = sigmoid(W2 @ silu(W1 @ ea + b1) + b2)
    float gacc = bg2[0];
#pragma unroll 4
    for (int j = 0; j < 32; j++) {
        float h = bg1_s[j];
#pragma unroll
        for (int i = 0; i < 16; i++) h += ea[i] * Wg1_s[i * 32 + j];
        gacc += (h * sigmoidf_(h)) * Wg2_s[j];
    }
    float gate = sigmoidf_(gacc);
    atomicAdd(&g_gatesum[tgt], gate);
    atomicAdd(&g_deg[tgt], 1.f);

    const float4* xlp = (const float4*)(g_xl + (size_t)src * 64);
    const float4* xrp = (const float4*)(g_xr + (size_t)tgt * 64);
    float alpha[4];
#pragma unroll
    for (int h = 0; h < 4; h++) {
        float acc = 0.f;
#pragma unroll
        for (int c4 = 0; c4 < 4; c4++) {
            float4 xl4 = xlp[h * 4 + c4];
            float4 xr4 = xrp[h * 4 + c4];
            int base = h * 16 + c4 * 4;
            float e0 = 0.f, e1 = 0.f, e2 = 0.f, e3 = 0.f;
#pragma unroll
            for (int i = 0; i < 16; i++) {
                float a = ea[i];
                const float* w = &We_s[i * 64 + base];
                e0 += a * w[0]; e1 += a * w[1];
                e2 += a * w[2]; e3 += a * w[3];
            }
            float m0 = xl4.x + xr4.x + e0; m0 = m0 > 0.f ? m0 : 0.2f * m0;
            float m1 = xl4.y + xr4.y + e1; m1 = m1 > 0.f ? m1 : 0.2f * m1;
            float m2 = xl4.z + xr4.z + e2; m2 = m2 > 0.f ? m2 : 0.2f * m2;
            float m3 = xl4.w + xr4.w + e3; m3 = m3 > 0.f ? m3 : 0.2f * m3;
            acc += m0 * att_s[base + 0] + m1 * att_s[base + 1] +
                   m2 * att_s[base + 2] + m3 * att_s[base + 3];
        }
        alpha[h] = acc;
        atomicMax(&g_amaxkey[tgt * 4 + h], f2key(acc));
    }
    g_alpha[e] = make_float4(alpha[0], alpha[1], alpha[2], alpha[3]);
}

// ---------------------------------------------------------------------------
// Kernel 3: a = exp(alpha - amax); denom += a; out[tgt] += xl[src] * a
// (division by denom is deferred to the node epilogue — linear in a)
// ---------------------------------------------------------------------------
__global__ void k_edge2(const int* __restrict__ ei, float* __restrict__ out) {
    int e = blockIdx.x * TPB + threadIdx.x;
    int src = ei[e];
    int tgt = ei[EE + e];
    float4 al = g_alpha[e];
    float a0 = __expf(al.x - key2f(g_amaxkey[tgt * 4 + 0]));
    float a1 = __expf(al.y - key2f(g_amaxkey[tgt * 4 + 1]));
    float a2 = __expf(al.z - key2f(g_amaxkey[tgt * 4 + 2]));
    float a3 = __expf(al.w - key2f(g_amaxkey[tgt * 4 + 3]));
    atomicAdd(&g_denom[tgt * 4 + 0], a0);
    atomicAdd(&g_denom[tgt * 4 + 1], a1);
    atomicAdd(&g_denom[tgt * 4 + 2], a2);
    atomicAdd(&g_denom[tgt * 4 + 3], a3);

    const float4* xlp = (const float4*)(g_xl + (size_t)src * 64);
    float* op = out + (size_t)tgt * 64;
    float ah[4] = {a0, a1, a2, a3};
#pragma unroll
    for (int h = 0; h < 4; h++) {
        float s = ah[h];
#pragma unroll
        for (int c4 = 0; c4 < 4; c4++) {
            float4 v = xlp[h * 4 + c4];
            red4(op + h * 16 + c4 * 4, v.x * s, v.y * s, v.z * s, v.w * s);
        }
    }
}

// ---------------------------------------------------------------------------
// Kernel 4: node epilogue — /denom, +bias, *mean_gate, LayerNorm, SiLU, +x
// one warp per node, 2 channels per lane
// ---------------------------------------------------------------------------
__global__ void k_final(const float* __restrict__ x,
                        const float* __restrict__ conv_bias,
                        const float* __restrict__ gamma,
                        const float* __restrict__ beta,
                        float* __restrict__ out) {
    int n = (blockIdx.x * blockDim.x + threadIdx.x) >> 5;
    int lane = threadIdx.x & 31;
    size_t base = (size_t)n * 64;

    float mg = g_gatesum[n] / fmaxf(g_deg[n], 1.f);
    float v[2];
#pragma unroll
    for (int k = 0; k < 2; k++) {
        int c = lane + 32 * k;
        int h = c >> 4;
        float den = g_denom[n * 4 + h];
        float inv = den > 0.f ? 1.f / den : 0.f;
        v[k] = (out[base + c] * inv + conv_bias[c]) * mg;
    }
    float s  = v[0] + v[1];
    float sq = v[0] * v[0] + v[1] * v[1];
#pragma unroll
    for (int o = 16; o > 0; o >>= 1) {
        s  += __shfl_xor_sync(0xFFFFFFFFu, s,  o);
        sq += __shfl_xor_sync(0xFFFFFFFFu, sq, o);
    }
    float mu   = s * (1.f / 64.f);
    float var  = sq * (1.f / 64.f) - mu * mu;
    float rstd = rsqrtf(var + 1e-5f);
#pragma unroll
    for (int k = 0; k < 2; k++) {
        int c = lane + 32 * k;
        float nv = (v[k] - mu) * rstd * gamma[c] + beta[c];
        nv = nv * sigmoidf_(nv);                 // SiLU
        out[base + c] = nv + x[base + c];        // residual
    }
}

// ---------------------------------------------------------------------------
extern "C" void kernel_launch(void* const* d_in, const int* in_sizes, int n_in,
                              void* d_out, int out_size) {
    const float* x         = (const float*)d_in[0];
    const int*   ei        = (const int*)  d_in[1];
    const float* edge_attr = (const float*)d_in[2];
    const float* Wl        = (const float*)d_in[3];
    const float* bl        = (const float*)d_in[4];
    const float* Wr        = (const float*)d_in[5];
    const float* br        = (const float*)d_in[6];
    const float* We        = (const float*)d_in[7];
    const float* att       = (const float*)d_in[8];
    const float* conv_bias = (const float*)d_in[9];
    const float* Wg1       = (const float*)d_in[10];
    const float* bg1       = (const float*)d_in[11];
    const float* Wg2       = (const float*)d_in[12];
    const float* bg2       = (const float*)d_in[13];
    const float* gamma     = (const float*)d_in[14];
    const float* beta      = (const float*)d_in[15];
    float* out = (float*)d_out;

    k_prep <<<NN / 4, TPB>>>(x, Wl, bl, Wr, br, out);
    k_edge1<<<EE / TPB, TPB>>>(ei, edge_attr, We, att, Wg1, bg1, Wg2, bg2);
    k_edge2<<<EE / TPB, TPB>>>(ei, out);
    k_final<<<NN * 32 / TPB, TPB>>>(x, conv_bias, gamma, beta, out);
}

// round 2
// speedup vs baseline: 1.3304x; 1.3304x over previous
#include <cuda_runtime.h>

#define NN 100000
#define EE 1600000
#define TPB 256

typedef unsigned long long u64;

// ---- scratch (__device__ globals; no allocations allowed) ----
__device__ float   g_xl[NN * 64];   // x @ Wl + bl   (source transform)
__device__ float   g_xr[NN * 64];   // x @ Wr + br   (target transform)
__device__ float4  g_denom[NN];     // per-head segment softmax denominators
__device__ float2  g_gate2[NN];     // {gate_sum, degree} per target

__device__ __forceinline__ float sigmoidf_(float v) {
    return 1.f / (1.f + __expf(-v));
}
__device__ __forceinline__ u64 pack2(float lo, float hi) {
    u64 r; asm("mov.b64 %0, {%1,%2};" : "=l"(r) : "f"(lo), "f"(hi)); return r;
}
__device__ __forceinline__ void unpack2(u64 v, float& lo, float& hi) {
    asm("mov.b64 {%0,%1}, %2;" : "=f"(lo), "=f"(hi) : "l"(v));
}
__device__ __forceinline__ void fma2(u64& d, u64 a, u64 b) {
    asm("fma.rn.f32x2 %0, %1, %2, %0;" : "+l"(d) : "l"(a), "l"(b));
}
__device__ __forceinline__ void red4(float* p, float a, float b, float c, float d) {
    asm volatile("red.global.add.v4.f32 [%0], {%1,%2,%3,%4};"
                 :: "l"(p), "f"(a), "f"(b), "f"(c), "f"(d) : "memory");
}
__device__ __forceinline__ void red2(float* p, float a, float b) {
    asm volatile("red.global.add.v2.f32 [%0], {%1,%2};"
                 :: "l"(p), "f"(a), "f"(b) : "memory");
}
__device__ __forceinline__ float leaky(float m) {
    return fmaxf(m, 0.f) + 0.2f * fminf(m, 0.f);
}

// ---------------------------------------------------------------------------
// Kernel 1: node transforms xl/xr + init accumulators (incl. zeroing d_out).
// 625 blocks, 160 nodes/block: weights staged ONCE per block.
// ---------------------------------------------------------------------------
#define PB  625
#define NPB 160
__global__ void k_prep(const float* __restrict__ x,
                       const float* __restrict__ Wl, const float* __restrict__ bl,
                       const float* __restrict__ Wr, const float* __restrict__ br,
                       float* __restrict__ out) {
    __shared__ float Wls[4096];
    __shared__ float Wrs[4096];
    __shared__ float xs[256];
    int t = threadIdx.x;
#pragma unroll
    for (int i = 0; i < 16; i++) {
        Wls[t + i * TPB] = Wl[t + i * TPB];
        Wrs[t + i * TPB] = Wr[t + i * TPB];
    }
    int nl = t >> 6, col = t & 63;
    float blv = bl[col], brv = br[col];

    for (int it = 0; it < NPB / 4; it++) {
        int nbase = blockIdx.x * NPB + it * 4;
        __syncthreads();
        xs[t] = x[(size_t)nbase * 64 + t];
        __syncthreads();

        int n = nbase + nl;
        float al = blv, ar = brv;
#pragma unroll
        for (int k = 0; k < 64; k++) {
            float xv = xs[nl * 64 + k];
            al += xv * Wls[k * 64 + col];
            ar += xv * Wrs[k * 64 + col];
        }
        g_xl[(size_t)n * 64 + col] = al;
        g_xr[(size_t)n * 64 + col] = ar;
        out[(size_t)n * 64 + col]  = 0.f;     // accumulate GAT output in d_out
        if (col == 0) g_denom[n] = make_float4(0.f, 0.f, 0.f, 0.f);
        if (col == 1) g_gate2[n] = make_float2(0.f, 0.f);
    }
}

// ---------------------------------------------------------------------------
// Kernel 2 (FUSED edge pass): gate MLP, attention logits, a = exp(alpha)
// (no max subtraction needed — ratios are invariant and |alpha| is small),
// denom accumulation, and weighted message scatter — all in one pass.
// Inner products use packed fma.rn.f32x2.
// ---------------------------------------------------------------------------
__global__ void __launch_bounds__(TPB) k_edge(
        const int* __restrict__ ei, const float* __restrict__ eag,
        const float* __restrict__ We, const float* __restrict__ att,
        const float* __restrict__ Wg1, const float* __restrict__ bg1,
        const float* __restrict__ Wg2, const float* __restrict__ bg2,
        float* __restrict__ out) {
    __shared__ __align__(16) float We_s[1024];   // [16,64]
    __shared__ __align__(16) float Wg1_s[512];   // [16,32]
    __shared__ __align__(8)  float bg1_s[32];
    __shared__ float Wg2_s[32];
    __shared__ float att_s[64];
    __shared__ float bg2_s;
    int t = threadIdx.x;
    for (int i = t; i < 1024; i += TPB) We_s[i] = We[i];
    for (int i = t; i < 512;  i += TPB) Wg1_s[i] = Wg1[i];
    if (t < 32) { Wg2_s[t] = Wg2[t]; bg1_s[t] = bg1[t]; }
    if (t < 64) att_s[t] = att[t];
    if (t == 0) bg2_s = bg2[0];
    __syncthreads();

    int e = blockIdx.x * TPB + t;   // E % TPB == 0
    int src = ei[e];
    int tgt = ei[EE + e];

    float ea[16];
    {
        const float4* eap = (const float4*)(eag + (size_t)e * 16);
#pragma unroll
        for (int i = 0; i < 4; i++) {
            float4 v = eap[i];
            ea[4 * i + 0] = v.x; ea[4 * i + 1] = v.y;
            ea[4 * i + 2] = v.z; ea[4 * i + 3] = v.w;
        }
    }

    // ---- edge gate: sigmoid(W2 @ silu(W1 @ ea + b1) + b2), packed f32x2 ----
    {
        u64 h2[16];
        const u64* bg1p = (const u64*)bg1_s;
#pragma unroll
        for (int j = 0; j < 16; j++) h2[j] = bg1p[j];
        const u64* wg1p = (const u64*)Wg1_s;
#pragma unroll
        for (int i = 0; i < 16; i++) {
            u64 a2 = pack2(ea[i], ea[i]);
#pragma unroll
            for (int j = 0; j < 16; j++) fma2(h2[j], a2, wg1p[i * 16 + j]);
        }
        float gacc = bg2_s;
#pragma unroll
        for (int j = 0; j < 16; j++) {
            float h0, h1; unpack2(h2[j], h0, h1);
            gacc += h0 * sigmoidf_(h0) * Wg2_s[2 * j] +
                    h1 * sigmoidf_(h1) * Wg2_s[2 * j + 1];
        }
        float gate = sigmoidf_(gacc);
        red2((float*)&g_gate2[tgt], gate, 1.f);
    }

    // ---- attention + message scatter, head by head ----
    u64 ea2[16];
#pragma unroll
    for (int i = 0; i < 16; i++) ea2[i] = pack2(ea[i], ea[i]);

    const float4* xlp = (const float4*)(g_xl + (size_t)src * 64);
    const float4* xrp = (const float4*)(g_xr + (size_t)tgt * 64);
    const u64* we2p = (const u64*)We_s;
    float* op = out + (size_t)tgt * 64;
    float ah[4];

#pragma unroll
    for (int h = 0; h < 4; h++) {
        float xlh[16];
        u64 s2[8];
#pragma unroll
        for (int c4 = 0; c4 < 4; c4++) {
            float4 l = xlp[h * 4 + c4];
            float4 r = xrp[h * 4 + c4];
            xlh[4 * c4 + 0] = l.x; xlh[4 * c4 + 1] = l.y;
            xlh[4 * c4 + 2] = l.z; xlh[4 * c4 + 3] = l.w;
            s2[2 * c4 + 0] = pack2(l.x + r.x, l.y + r.y);
            s2[2 * c4 + 1] = pack2(l.z + r.z, l.w + r.w);
        }
#pragma unroll
        for (int i = 0; i < 16; i++) {
#pragma unroll
            for (int p = 0; p < 8; p++)
                fma2(s2[p], ea2[i], we2p[i * 32 + h * 8 + p]);
        }
        float acc = 0.f;
#pragma unroll
        for (int p = 0; p < 8; p++) {
            float m0, m1; unpack2(s2[p], m0, m1);
            acc += leaky(m0) * att_s[h * 16 + 2 * p] +
                   leaky(m1) * att_s[h * 16 + 2 * p + 1];
        }
        float a = __expf(acc);   // no max-shift: ratios identical, range safe
        ah[h] = a;
#pragma unroll
        for (int c4 = 0; c4 < 4; c4++)
            red4(op + h * 16 + c4 * 4,
                 xlh[4 * c4 + 0] * a, xlh[4 * c4 + 1] * a,
                 xlh[4 * c4 + 2] * a, xlh[4 * c4 + 3] * a);
    }
    red4((float*)&g_denom[tgt], ah[0], ah[1], ah[2], ah[3]);
}

// ---------------------------------------------------------------------------
// Kernel 3: node epilogue — /denom, +bias, *mean_gate, LayerNorm, SiLU, +x.
// One warp per node, 2 consecutive channels per lane (float2 I/O).
// ---------------------------------------------------------------------------
__global__ void k_final(const float* __restrict__ x,
                        const float* __restrict__ conv_bias,
                        const float* __restrict__ gamma,
                        const float* __restrict__ beta,
                        float* __restrict__ out) {
    int n = (blockIdx.x * blockDim.x + threadIdx.x) >> 5;
    int lane = threadIdx.x & 31;
    size_t b2 = (size_t)n * 32 + lane;

    float2 gd = g_gate2[n];
    float mg = gd.x / fmaxf(gd.y, 1.f);

    float4 den4 = g_denom[n];
    int h = lane >> 3;
    float den = (h == 0) ? den4.x : (h == 1) ? den4.y : (h == 2) ? den4.z : den4.w;
    float inv = den > 0.f ? 1.f / den : 0.f;

    float2 o  = ((const float2*)out)[b2];
    float2 cb = ((const float2*)conv_bias)[lane];
    float v0 = (o.x * inv + cb.x) * mg;
    float v1 = (o.y * inv + cb.y) * mg;

    float s  = v0 + v1;
    float sq = v0 * v0 + v1 * v1;
#pragma unroll
    for (int ofs = 16; ofs > 0; ofs >>= 1) {
        s  += __shfl_xor_sync(0xFFFFFFFFu, s,  ofs);
        sq += __shfl_xor_sync(0xFFFFFFFFu, sq, ofs);
    }
    float mu   = s * (1.f / 64.f);
    float var  = sq * (1.f / 64.f) - mu * mu;
    float rstd = rsqrtf(var + 1e-5f);

    float2 g  = ((const float2*)gamma)[lane];
    float2 bt = ((const float2*)beta)[lane];
    float2 xv = ((const float2*)x)[b2];
    float n0 = (v0 - mu) * rstd * g.x + bt.x;
    float n1 = (v1 - mu) * rstd * g.y + bt.y;
    n0 = n0 * sigmoidf_(n0);
    n1 = n1 * sigmoidf_(n1);
    ((float2*)out)[b2] = make_float2(n0 + xv.x, n1 + xv.y);
}

// ---------------------------------------------------------------------------
extern "C" void kernel_launch(void* const* d_in, const int* in_sizes, int n_in,
                              void* d_out, int out_size) {
    const float* x         = (const float*)d_in[0];
    const int*   ei        = (const int*)  d_in[1];
    const float* edge_attr = (const float*)d_in[2];
    const float* Wl        = (const float*)d_in[3];
    const float* bl        = (const float*)d_in[4];
    const float* Wr        = (const float*)d_in[5];
    const float* br        = (const float*)d_in[6];
    const float* We        = (const float*)d_in[7];
    const float* att       = (const float*)d_in[8];
    const float* conv_bias = (const float*)d_in[9];
    const float* Wg1       = (const float*)d_in[10];
    const float* bg1       = (const float*)d_in[11];
    const float* Wg2       = (const float*)d_in[12];
    const float* bg2       = (const float*)d_in[13];
    const float* gamma     = (const float*)d_in[14];
    const float* beta      = (const float*)d_in[15];
    float* out = (float*)d_out;

    k_prep <<<PB, TPB>>>(x, Wl, bl, Wr, br, out);
    k_edge <<<EE / TPB, TPB>>>(ei, edge_attr, We, att, Wg1, bg1, Wg2, bg2, out);
    k_final<<<NN * 32 / TPB, TPB>>>(x, conv_bias, gamma, beta, out);
}

// round 3
// speedup vs baseline: 1.7144x; 1.2886x over previous
#include <cuda_runtime.h>

#define NN 100000
#define EE 1600000
#define TPB 256

typedef unsigned long long u64;

// ---- scratch (__device__ globals; no allocations allowed) ----
__device__ float   g_xl[NN * 64];   // x @ Wl + bl   (source transform)
__device__ float   g_xr[NN * 64];   // x @ Wr + br   (target transform)
__device__ float4  g_denom[NN];     // per-head segment softmax denominators
__device__ float2  g_gate2[NN];     // {gate_sum, degree} per target

__device__ __forceinline__ float sigmoidf_(float v) {
    return 1.f / (1.f + __expf(-v));
}
__device__ __forceinline__ u64 pack2(float lo, float hi) {
    u64 r; asm("mov.b64 %0, {%1,%2};" : "=l"(r) : "f"(lo), "f"(hi)); return r;
}
__device__ __forceinline__ void unpack2(u64 v, float& lo, float& hi) {
    asm("mov.b64 {%0,%1}, %2;" : "=f"(lo), "=f"(hi) : "l"(v));
}
__device__ __forceinline__ void fma2(u64& d, u64 a, u64 b) {
    asm("fma.rn.f32x2 %0, %1, %2, %0;" : "+l"(d) : "l"(a), "l"(b));
}
__device__ __forceinline__ void red4(float* p, float a, float b, float c, float d) {
    asm volatile("red.global.add.v4.f32 [%0], {%1,%2,%3,%4};"
                 :: "l"(p), "f"(a), "f"(b), "f"(c), "f"(d) : "memory");
}
__device__ __forceinline__ void red2(float* p, float a, float b) {
    asm volatile("red.global.add.v2.f32 [%0], {%1,%2};"
                 :: "l"(p), "f"(a), "f"(b) : "memory");
}
__device__ __forceinline__ float leaky(float m) {
    return fmaxf(m, 0.f) + 0.2f * fminf(m, 0.f);
}
__device__ __forceinline__ void cpa16(float* smem_dst, const float* gsrc) {
    unsigned d = (unsigned)__cvta_generic_to_shared(smem_dst);
    asm volatile("cp.async.cg.shared.global [%0], [%1], 16;"
                 :: "r"(d), "l"(gsrc) : "memory");
}

// ---------------------------------------------------------------------------
// Kernel 1: node transforms xl/xr (fused W = [Wl | Wr]) + init accumulators.
// Register-tiled: thread = 8 nodes x 4 cols, f32x2 accumulators.
// Per k: 2 broadcast LDS.128 (x) + 1 LDS.128 (W) -> 16 FFMA2.
// ---------------------------------------------------------------------------
__global__ void __launch_bounds__(256) k_prep(
        const float* __restrict__ x,
        const float* __restrict__ Wl, const float* __restrict__ bl,
        const float* __restrict__ Wr, const float* __restrict__ br,
        float* __restrict__ out) {
    __shared__ __align__(16) float Ws[64 * 128];   // [k][128 cols: xl|xr]
    __shared__ __align__(16) float xs[64 * 64];    // [node][k]
    int t = threadIdx.x;
    int nb = blockIdx.x * 64;

#pragma unroll
    for (int i = 0; i < 16; i++) {
        int idx = t + i * 256;                     // 4096 weight entries per mat
        int k = idx >> 6, c = idx & 63;
        Ws[k * 128 + c]      = Wl[idx];
        Ws[k * 128 + 64 + c] = Wr[idx];
    }
#pragma unroll
    for (int i = 0; i < 16; i++) {
        int idx = t + i * 256;
        int n = nb + (idx >> 6);
        bool ok = n < NN;
        xs[idx] = ok ? x[(size_t)n * 64 + (idx & 63)] : 0.f;
        if (ok) out[(size_t)n * 64 + (idx & 63)] = 0.f;
    }
    if (t < 64) {
        int n = nb + t;
        if (n < NN) {
            g_denom[n] = make_float4(0.f, 0.f, 0.f, 0.f);
            g_gate2[n] = make_float2(0.f, 0.f);
        }
    }
    __syncthreads();

    int cg = t & 31, ng = t >> 5;     // warp = one node group (broadcast x)
    int c0 = cg * 4;
    const float* bsrc = (c0 < 64) ? (bl + c0) : (br + (c0 - 64));
    float4 bias = *(const float4*)bsrc;

    u64 acc[8][2];
#pragma unroll
    for (int j = 0; j < 8; j++) {
        acc[j][0] = pack2(bias.x, bias.y);
        acc[j][1] = pack2(bias.z, bias.w);
    }

    for (int k4 = 0; k4 < 16; k4++) {
        float4 xv[8];
#pragma unroll
        for (int j = 0; j < 8; j++)
            xv[j] = *(const float4*)&xs[(ng * 8 + j) * 64 + k4 * 4];
#pragma unroll
        for (int kk = 0; kk < 4; kk++) {
            float4 wv = *(const float4*)&Ws[(k4 * 4 + kk) * 128 + c0];
            u64 w01 = pack2(wv.x, wv.y), w23 = pack2(wv.z, wv.w);
#pragma unroll
            for (int j = 0; j < 8; j++) {
                float xsc = (kk == 0) ? xv[j].x : (kk == 1) ? xv[j].y
                          : (kk == 2) ? xv[j].z : xv[j].w;
                u64 xx = pack2(xsc, xsc);
                fma2(acc[j][0], xx, w01);
                fma2(acc[j][1], xx, w23);
            }
        }
    }

    float* dst = (c0 < 64) ? g_xl : g_xr;
    int cc = c0 & 63;
#pragma unroll
    for (int j = 0; j < 8; j++) {
        int n = nb + ng * 8 + j;
        if (n < NN) {
            float o0, o1, o2, o3;
            unpack2(acc[j][0], o0, o1);
            unpack2(acc[j][1], o2, o3);
            *(float4*)&dst[(size_t)n * 64 + cc] = make_float4(o0, o1, o2, o3);
        }
    }
}

// ---------------------------------------------------------------------------
// Kernel 2 (fused edge pass, warp-cooperative gathers/scatters):
//  A: cp.async-stage the warp's 32 xl[src] / xr[tgt] rows (4 wf/instr)
//     overlapped with coalesced ea load + gate MLP (f32x2)
//  B: per-thread attention per head from conflict-free smem (pad 68);
//     scaled messages overwrite the xr stage in place
//  C: cooperative red.v4 scatter of full 256B message rows (4 wf/instr)
// ---------------------------------------------------------------------------
#define ETPB 64   // 2 warps per block, 64 edges per block
__global__ void __launch_bounds__(ETPB) k_edge(
        const int* __restrict__ ei, const float* __restrict__ eag,
        const float* __restrict__ We, const float* __restrict__ att,
        const float* __restrict__ Wg1, const float* __restrict__ bg1,
        const float* __restrict__ Wg2, const float* __restrict__ bg2,
        float* __restrict__ out) {
    __shared__ __align__(16) float We_s[1024];          // [16,64]
    __shared__ __align__(16) float Wg1_s[512];          // [16,32]
    __shared__ __align__(16) float stg[2][2][32][68];   // [warp][xl|msg][row][col]
    __shared__ __align__(8)  float bg1_s[32];
    __shared__ float Wg2_s[32];
    __shared__ float att_s[64];
    __shared__ float bg2_s;

    int t = threadIdx.x, lane = t & 31, w = t >> 5;
    for (int i = t; i < 1024; i += ETPB) We_s[i] = We[i];
    for (int i = t; i < 512;  i += ETPB) Wg1_s[i] = Wg1[i];
    if (t < 32) { bg1_s[t] = bg1[t]; Wg2_s[t] = Wg2[t]; }
    att_s[t] = att[t];           // 64 threads cover all 64
    if (t == 0) bg2_s = bg2[0];
    __syncthreads();

    int e = blockIdx.x * ETPB + t;          // EE % ETPB == 0
    int src = ei[e];
    int tgt = ei[EE + e];

    // ---- phase A: cooperative row staging via cp.async ----
    int cofs = (lane & 15) * 4;             // 16 lanes cover a 256B row
    int rsel = lane >> 4;                   // 2 rows per instruction
#pragma unroll
    for (int i = 0; i < 16; i++) {
        int r  = 2 * i + rsel;
        int s  = __shfl_sync(0xFFFFFFFFu, src, r);
        int tg = __shfl_sync(0xFFFFFFFFu, tgt, r);
        cpa16(&stg[w][0][r][cofs], g_xl + (size_t)s  * 64 + cofs);
        cpa16(&stg[w][1][r][cofs], g_xr + (size_t)tg * 64 + cofs);
    }
    asm volatile("cp.async.commit_group;" ::: "memory");

    // ---- overlap: ea load (packed) + gate MLP ----
    u64 ea2[16];
    {
        const float4* eap = (const float4*)(eag + (size_t)e * 16);
#pragma unroll
        for (int i = 0; i < 4; i++) {
            float4 v = eap[i];
            ea2[4 * i + 0] = pack2(v.x, v.x);
            ea2[4 * i + 1] = pack2(v.y, v.y);
            ea2[4 * i + 2] = pack2(v.z, v.z);
            ea2[4 * i + 3] = pack2(v.w, v.w);
        }
    }
    {
        u64 h2[16];
        const u64* bg1p = (const u64*)bg1_s;
#pragma unroll
        for (int j = 0; j < 16; j++) h2[j] = bg1p[j];
        const u64* wg1p = (const u64*)Wg1_s;
#pragma unroll
        for (int i = 0; i < 16; i++) {
#pragma unroll
            for (int j = 0; j < 16; j++) fma2(h2[j], ea2[i], wg1p[i * 16 + j]);
        }
        float gacc = bg2_s;
#pragma unroll
        for (int j = 0; j < 16; j++) {
            float h0, h1; unpack2(h2[j], h0, h1);
            gacc += h0 * sigmoidf_(h0) * Wg2_s[2 * j] +
                    h1 * sigmoidf_(h1) * Wg2_s[2 * j + 1];
        }
        red2((float*)&g_gate2[tgt], sigmoidf_(gacc), 1.f);
    }

    asm volatile("cp.async.wait_group 0;" ::: "memory");
    __syncwarp();

    // ---- phase B: per-head attention; write scaled msgs back into stage 1 ----
    const u64* we2p = (const u64*)We_s;
    float ah[4];
#pragma unroll
    for (int h = 0; h < 4; h++) {
        float4 xl4[4], xr4[4];
#pragma unroll
        for (int c4 = 0; c4 < 4; c4++) {
            xl4[c4] = *(const float4*)&stg[w][0][lane][h * 16 + c4 * 4];
            xr4[c4] = *(const float4*)&stg[w][1][lane][h * 16 + c4 * 4];
        }
        u64 s2[8];
#pragma unroll
        for (int c4 = 0; c4 < 4; c4++) {
            s2[2 * c4 + 0] = pack2(xl4[c4].x + xr4[c4].x, xl4[c4].y + xr4[c4].y);
            s2[2 * c4 + 1] = pack2(xl4[c4].z + xr4[c4].z, xl4[c4].w + xr4[c4].w);
        }
#pragma unroll
        for (int i = 0; i < 16; i++) {
#pragma unroll
            for (int p = 0; p < 8; p++)
                fma2(s2[p], ea2[i], we2p[i * 32 + h * 8 + p]);
        }
        float acc = 0.f;
#pragma unroll
        for (int p = 0; p < 8; p++) {
            float m0, m1; unpack2(s2[p], m0, m1);
            acc += leaky(m0) * att_s[h * 16 + 2 * p] +
                   leaky(m1) * att_s[h * 16 + 2 * p + 1];
        }
        float a = __expf(acc);    // no max-shift: ratios invariant, range safe
        ah[h] = a;
#pragma unroll
        for (int c4 = 0; c4 < 4; c4++) {
            float4 v = xl4[c4];
            *(float4*)&stg[w][1][lane][h * 16 + c4 * 4] =
                make_float4(v.x * a, v.y * a, v.z * a, v.w * a);
        }
    }
    red4((float*)&g_denom[tgt], ah[0], ah[1], ah[2], ah[3]);
    __syncwarp();

    // ---- phase C: cooperative scatter of 256B message rows ----
#pragma unroll
    for (int i = 0; i < 16; i++) {
        int r  = 2 * i + rsel;
        int tg = __shfl_sync(0xFFFFFFFFu, tgt, r);
        float4 v = *(const float4*)&stg[w][1][r][cofs];
        red4(out + (size_t)tg * 64 + cofs, v.x, v.y, v.z, v.w);
    }
}

// ---------------------------------------------------------------------------
// Kernel 3: node epilogue — /denom, +bias, *mean_gate, LayerNorm, SiLU, +x.
// ---------------------------------------------------------------------------
__global__ void k_final(const float* __restrict__ x,
                        const float* __restrict__ conv_bias,
                        const float* __restrict__ gamma,
                        const float* __restrict__ beta,
                        float* __restrict__ out) {
    int n = (blockIdx.x * blockDim.x + threadIdx.x) >> 5;
    int lane = threadIdx.x & 31;
    size_t b2 = (size_t)n * 32 + lane;

    float2 gd = g_gate2[n];
    float mg = gd.x / fmaxf(gd.y, 1.f);

    float4 den4 = g_denom[n];
    int h = lane >> 3;
    float den = (h == 0) ? den4.x : (h == 1) ? den4.y : (h == 2) ? den4.z : den4.w;
    float inv = den > 0.f ? 1.f / den : 0.f;

    float2 o  = ((const float2*)out)[b2];
    float2 cb = ((const float2*)conv_bias)[lane];
    float v0 = (o.x * inv + cb.x) * mg;
    float v1 = (o.y * inv + cb.y) * mg;

    float s  = v0 + v1;
    float sq = v0 * v0 + v1 * v1;
#pragma unroll
    for (int ofs = 16; ofs > 0; ofs >>= 1) {
        s  += __shfl_xor_sync(0xFFFFFFFFu, s,  ofs);
        sq += __shfl_xor_sync(0xFFFFFFFFu, sq, ofs);
    }
    float mu   = s * (1.f / 64.f);
    float var  = sq * (1.f / 64.f) - mu * mu;
    float rstd = rsqrtf(var + 1e-5f);

    float2 g  = ((const float2*)gamma)[lane];
    float2 bt = ((const float2*)beta)[lane];
    float2 xv = ((const float2*)x)[b2];
    float n0 = (v0 - mu) * rstd * g.x + bt.x;
    float n1 = (v1 - mu) * rstd * g.y + bt.y;
    n0 = n0 * sigmoidf_(n0);
    n1 = n1 * sigmoidf_(n1);
    ((float2*)out)[b2] = make_float2(n0 + xv.x, n1 + xv.y);
}

// ---------------------------------------------------------------------------
extern "C" void kernel_launch(void* const* d_in, const int* in_sizes, int n_in,
                              void* d_out, int out_size) {
    const float* x         = (const float*)d_in[0];
    const int*   ei        = (const int*)  d_in[1];
    const float* edge_attr = (const float*)d_in[2];
    const float* Wl        = (const float*)d_in[3];
    const float* bl        = (const float*)d_in[4];
    const float* Wr        = (const float*)d_in[5];
    const float* br        = (const float*)d_in[6];
    const float* We        = (const float*)d_in[7];
    const float* att       = (const float*)d_in[8];
    const float* conv_bias = (const float*)d_in[9];
    const float* Wg1       = (const float*)d_in[10];
    const float* bg1       = (const float*)d_in[11];
    const float* Wg2       = (const float*)d_in[12];
    const float* bg2       = (const float*)d_in[13];
    const float* gamma     = (const float*)d_in[14];
    const float* beta      = (const float*)d_in[15];
    float* out = (float*)d_out;

    k_prep <<<(NN + 63) / 64, 256>>>(x, Wl, bl, Wr, br, out);
    k_edge <<<EE / ETPB, ETPB>>>(ei, edge_attr, We, att, Wg1, bg1, Wg2, bg2, out);
    k_final<<<NN * 32 / TPB, TPB>>>(x, conv_bias, gamma, beta, out);
}

// round 4
// speedup vs baseline: 2.5008x; 1.4587x over previous
#include <cuda_runtime.h>

#define NN 100000
#define EE 1600000
#define TPB 256

typedef unsigned long long u64;

// ---- scratch (__device__ globals; no allocations allowed) ----
__device__ float   g_xl[NN * 64];   // x @ Wl + bl   (source transform)
__device__ float   g_xr[NN * 64];   // x @ Wr + br   (target transform)
__device__ float4  g_denom[NN];     // per-head segment softmax denominators
__device__ float2  g_gate2[NN];     // {gate_sum, degree} per target

// ---- small params in constant memory (uniform-port reads, frees smem) ----
__constant__ __align__(16) float cWe[1024];   // [16,64]
__constant__ __align__(16) float cWg1[512];   // [16,32]
__constant__ __align__(16) float cWg2[32];
__constant__ __align__(16) float cbg1[32];
__constant__ __align__(16) float catt[64];
__constant__ __align__(16) float cbias[64];
__constant__ __align__(16) float cgamma[64];
__constant__ __align__(16) float cbeta[64];
__constant__ float cbg2[1];

__device__ __forceinline__ float sigmoidf_(float v) {
    return 1.f / (1.f + __expf(-v));
}
__device__ __forceinline__ u64 pack2(float lo, float hi) {
    u64 r; asm("mov.b64 %0, {%1,%2};" : "=l"(r) : "f"(lo), "f"(hi)); return r;
}
__device__ __forceinline__ void unpack2(u64 v, float& lo, float& hi) {
    asm("mov.b64 {%0,%1}, %2;" : "=f"(lo), "=f"(hi) : "l"(v));
}
__device__ __forceinline__ void fma2(u64& d, u64 a, u64 b) {
    asm("fma.rn.f32x2 %0, %1, %2, %0;" : "+l"(d) : "l"(a), "l"(b));
}
__device__ __forceinline__ void red4(float* p, float a, float b, float c, float d) {
    asm volatile("red.global.add.v4.f32 [%0], {%1,%2,%3,%4};"
                 :: "l"(p), "f"(a), "f"(b), "f"(c), "f"(d) : "memory");
}
__device__ __forceinline__ void red2(float* p, float a, float b) {
    asm volatile("red.global.add.v2.f32 [%0], {%1,%2};"
                 :: "l"(p), "f"(a), "f"(b) : "memory");
}
__device__ __forceinline__ float leaky(float m) {     // slope 0.2 < 1
    return fmaxf(m, 0.2f * m);
}
__device__ __forceinline__ void cpa16(float* smem_dst, const float* gsrc) {
    unsigned d = (unsigned)__cvta_generic_to_shared(smem_dst);
    asm volatile("cp.async.cg.shared.global [%0], [%1], 16;"
                 :: "r"(d), "l"(gsrc) : "memory");
}

// ---------------------------------------------------------------------------
// Kernel 1: node transforms (fused W = [Wl|Wr]) + init accumulators.
// x rows read directly via broadcast LDG (warp-uniform) — no x staging.
// ---------------------------------------------------------------------------
__global__ void __launch_bounds__(256) k_prep(
        const float* __restrict__ x,
        const float* __restrict__ Wl, const float* __restrict__ bl,
        const float* __restrict__ Wr, const float* __restrict__ br,
        float* __restrict__ out) {
    __shared__ __align__(16) float Ws[64 * 128];   // [k][128 cols: xl|xr]
    int t = threadIdx.x;
    int nb = blockIdx.x * 64;

#pragma unroll
    for (int i = 0; i < 16; i++) {
        int idx = t + i * 256;
        int k = idx >> 6, c = idx & 63;
        Ws[k * 128 + c]      = Wl[idx];
        Ws[k * 128 + 64 + c] = Wr[idx];
    }
#pragma unroll
    for (int i = 0; i < 16; i++) {     // zero d_out for this node tile
        int idx = t + i * 256;
        int n = nb + (idx >> 6);
        if (n < NN) out[(size_t)n * 64 + (idx & 63)] = 0.f;
    }
    if (t < 64) {
        int n = nb + t;
        if (n < NN) {
            g_denom[n] = make_float4(0.f, 0.f, 0.f, 0.f);
            g_gate2[n] = make_float2(0.f, 0.f);
        }
    }
    __syncthreads();

    int cg = t & 31, ng = t >> 5;      // warp = one 8-node group (broadcast x)
    int c0 = cg * 4;
    const float* bsrc = (c0 < 64) ? (bl + c0) : (br + (c0 - 64));
    float4 bias = *(const float4*)bsrc;

    u64 acc[8][2];
#pragma unroll
    for (int j = 0; j < 8; j++) {
        acc[j][0] = pack2(bias.x, bias.y);
        acc[j][1] = pack2(bias.z, bias.w);
    }

    int nlim = NN - nb;                // nodes valid in this tile
    for (int k4 = 0; k4 < 16; k4++) {
        float4 xv[8];
#pragma unroll
        for (int j = 0; j < 8; j++) {
            int nl = ng * 8 + j;
            xv[j] = (nl < nlim)
                  ? *(const float4*)&x[(size_t)(nb + nl) * 64 + k4 * 4]
                  : make_float4(0.f, 0.f, 0.f, 0.f);
        }
#pragma unroll
        for (int kk = 0; kk < 4; kk++) {
            float4 wv = *(const float4*)&Ws[(k4 * 4 + kk) * 128 + c0];
            u64 w01 = pack2(wv.x, wv.y), w23 = pack2(wv.z, wv.w);
#pragma unroll
            for (int j = 0; j < 8; j++) {
                float xsc = (kk == 0) ? xv[j].x : (kk == 1) ? xv[j].y
                          : (kk == 2) ? xv[j].z : xv[j].w;
                u64 xx = pack2(xsc, xsc);
                fma2(acc[j][0], xx, w01);
                fma2(acc[j][1], xx, w23);
            }
        }
    }

    float* dst = (c0 < 64) ? g_xl : g_xr;
    int cc = c0 & 63;
#pragma unroll
    for (int j = 0; j < 8; j++) {
        int n = nb + ng * 8 + j;
        if (n < NN) {
            float o0, o1, o2, o3;
            unpack2(acc[j][0], o0, o1);
            unpack2(acc[j][1], o2, o3);
            *(float4*)&dst[(size_t)n * 64 + cc] = make_float4(o0, o1, o2, o3);
        }
    }
}

// ---------------------------------------------------------------------------
// Kernel 2 (fused edge pass), 128 threads / 4 warps, dynamic smem:
//   stgL: full xl rows per warp     [32][68]  (msgs overwrite in place)
//   stgR: per-head xr 64B chunks, double-buffered [2][32][20]
// cp.async software pipeline: heads staged 2 ahead; gate MLP overlaps.
// ---------------------------------------------------------------------------
#define ETPB 128
#define L_STRIDE 68
#define R_STRIDE 20
#define L_WARP   (32 * L_STRIDE)              // 2176 floats
#define R_WARP   (2 * 32 * R_STRIDE)          // 1280 floats
#define EDGE_SMEM ((4 * (L_WARP + R_WARP)) * 4)   // 55296 bytes

extern __shared__ float sdyn[];

__global__ void __launch_bounds__(ETPB) k_edge(
        const int* __restrict__ ei, const float* __restrict__ eag,
        float* __restrict__ out) {
    int t = threadIdx.x, lane = t & 31, w = t >> 5;
    float* L  = sdyn + w * L_WARP;                    // [32][68]
    float* R  = sdyn + 4 * L_WARP + w * R_WARP;       // [2][32][20]

    int e = blockIdx.x * ETPB + t;          // EE % ETPB == 0
    int src = ei[e];
    int tgt = ei[EE + e];

    // ---- phase A: cooperative staging via cp.async ----
    int cofs = (lane & 15) * 4;             // 16 lanes cover a 256B row
    int rsel = lane >> 4;
    int c4h  = (lane & 3) * 4;              // 4 lanes cover a 64B head chunk
    int r8   = lane >> 2;

    // xl full rows + xr head 0  -> group 0
#pragma unroll
    for (int i = 0; i < 16; i++) {
        int r = 2 * i + rsel;
        int s = __shfl_sync(0xFFFFFFFFu, src, r);
        cpa16(&L[r * L_STRIDE + cofs], g_xl + (size_t)s * 64 + cofs);
    }
#pragma unroll
    for (int i = 0; i < 4; i++) {
        int r  = 8 * i + r8;
        int tg = __shfl_sync(0xFFFFFFFFu, tgt, r);
        cpa16(&R[r * R_STRIDE + c4h], g_xr + (size_t)tg * 64 + c4h);
    }
    asm volatile("cp.async.commit_group;" ::: "memory");
    // xr head 1 -> group 1
#pragma unroll
    for (int i = 0; i < 4; i++) {
        int r  = 8 * i + r8;
        int tg = __shfl_sync(0xFFFFFFFFu, tgt, r);
        cpa16(&R[640 + r * R_STRIDE + c4h], g_xr + (size_t)tg * 64 + 16 + c4h);
    }
    asm volatile("cp.async.commit_group;" ::: "memory");

    // ---- overlap: ea load + gate MLP (constants via uniform port) ----
    u64 ea2[16];
    {
        const float4* eap = (const float4*)(eag + (size_t)e * 16);
#pragma unroll
        for (int i = 0; i < 4; i++) {
            float4 v = eap[i];
            ea2[4 * i + 0] = pack2(v.x, v.x);
            ea2[4 * i + 1] = pack2(v.y, v.y);
            ea2[4 * i + 2] = pack2(v.z, v.z);
            ea2[4 * i + 3] = pack2(v.w, v.w);
        }
    }
    {
        u64 h2[16];
        const u64* bg1p = (const u64*)cbg1;
#pragma unroll
        for (int j = 0; j < 16; j++) h2[j] = bg1p[j];
        const u64* wg1p = (const u64*)cWg1;
#pragma unroll
        for (int i = 0; i < 16; i++)
#pragma unroll
            for (int j = 0; j < 16; j++) fma2(h2[j], ea2[i], wg1p[i * 16 + j]);
        float gacc = cbg2[0];
#pragma unroll
        for (int j = 0; j < 16; j++) {
            float h0, h1; unpack2(h2[j], h0, h1);
            gacc += h0 * sigmoidf_(h0) * cWg2[2 * j] +
                    h1 * sigmoidf_(h1) * cWg2[2 * j + 1];
        }
        red2((float*)&g_gate2[tgt], sigmoidf_(gacc), 1.f);
    }

    // ---- phase B: per-head attention, pipelined xr staging ----
    const u64* we2p = (const u64*)cWe;
    float ah[4];
#pragma unroll
    for (int h = 0; h < 4; h++) {
        if (h < 3) asm volatile("cp.async.wait_group 1;" ::: "memory");
        else       asm volatile("cp.async.wait_group 0;" ::: "memory");
        __syncwarp();

        float* Rb = R + (h & 1) * 640;
        float4 xl4[4], xr4[4];
#pragma unroll
        for (int c4 = 0; c4 < 4; c4++) {
            xl4[c4] = *(const float4*)&L[lane * L_STRIDE + h * 16 + c4 * 4];
            xr4[c4] = *(const float4*)&Rb[lane * R_STRIDE + c4 * 4];
        }
        u64 s2[8];
#pragma unroll
        for (int c4 = 0; c4 < 4; c4++) {
            s2[2 * c4 + 0] = pack2(xl4[c4].x + xr4[c4].x, xl4[c4].y + xr4[c4].y);
            s2[2 * c4 + 1] = pack2(xl4[c4].z + xr4[c4].z, xl4[c4].w + xr4[c4].w);
        }
#pragma unroll
        for (int i = 0; i < 16; i++)
#pragma unroll
            for (int p = 0; p < 8; p++)
                fma2(s2[p], ea2[i], we2p[i * 32 + h * 8 + p]);
        float acc = 0.f;
#pragma unroll
        for (int p = 0; p < 8; p++) {
            float m0, m1; unpack2(s2[p], m0, m1);
            acc += leaky(m0) * catt[h * 16 + 2 * p] +
                   leaky(m1) * catt[h * 16 + 2 * p + 1];
        }
        float a = __expf(acc);     // no max-shift: ratios invariant, range safe
        ah[h] = a;
#pragma unroll
        for (int c4 = 0; c4 < 4; c4++) {
            float4 v = xl4[c4];
            *(float4*)&L[lane * L_STRIDE + h * 16 + c4 * 4] =
                make_float4(v.x * a, v.y * a, v.z * a, v.w * a);
        }
        __syncwarp();
        if (h < 2) {              // stage head h+2 into buffer (h&1)
#pragma unroll
            for (int i = 0; i < 4; i++) {
                int r  = 8 * i + r8;
                int tg = __shfl_sync(0xFFFFFFFFu, tgt, r);
                cpa16(&R[(h & 1) * 640 + r * R_STRIDE + c4h],
                      g_xr + (size_t)tg * 64 + (h + 2) * 16 + c4h);
            }
            asm volatile("cp.async.commit_group;" ::: "memory");
        }
    }
    red4((float*)&g_denom[tgt], ah[0], ah[1], ah[2], ah[3]);
    __syncwarp();

    // ---- phase C: cooperative scatter of 256B message rows ----
#pragma unroll
    for (int i = 0; i < 16; i++) {
        int r  = 2 * i + rsel;
        int tg = __shfl_sync(0xFFFFFFFFu, tgt, r);
        float4 v = *(const float4*)&L[r * L_STRIDE + cofs];
        red4(out + (size_t)tg * 64 + cofs, v.x, v.y, v.z, v.w);
    }
}

// ---------------------------------------------------------------------------
// Kernel 3: node epilogue — 16 threads/node, float4 lanes, constant params.
// ---------------------------------------------------------------------------
__global__ void k_final(const float* __restrict__ x, float* __restrict__ out) {
    int gid = blockIdx.x * blockDim.x + threadIdx.x;
    int n = gid >> 4;
    int q = threadIdx.x & 15;            // float4 chunk 0..15
    int h = q >> 2;                      // head

    float2 gd = g_gate2[n];
    float mg = gd.x / fmaxf(gd.y, 1.f);
    float4 den4 = g_denom[n];
    float den = (h == 0) ? den4.x : (h == 1) ? den4.y : (h == 2) ? den4.z : den4.w;
    float inv = den > 0.f ? 1.f / den : 0.f;

    size_t idx = (size_t)n * 16 + q;
    float4 o  = ((const float4*)out)[idx];
    float4 cb = ((const float4*)cbias)[q];
    float4 v;
    v.x = (o.x * inv + cb.x) * mg;
    v.y = (o.y * inv + cb.y) * mg;
    v.z = (o.z * inv + cb.z) * mg;
    v.w = (o.w * inv + cb.w) * mg;

    float s  = v.x + v.y + v.z + v.w;
    float sq = v.x * v.x + v.y * v.y + v.z * v.z + v.w * v.w;
#pragma unroll
    for (int ofs = 1; ofs < 16; ofs <<= 1) {
        s  += __shfl_xor_sync(0xFFFFFFFFu, s,  ofs);
        sq += __shfl_xor_sync(0xFFFFFFFFu, sq, ofs);
    }
    float mu   = s * (1.f / 64.f);
    float var  = sq * (1.f / 64.f) - mu * mu;
    float rstd = rsqrtf(var + 1e-5f);

    float4 g  = ((const float4*)cgamma)[q];
    float4 bt = ((const float4*)cbeta)[q];
    float4 xv = ((const float4*)x)[idx];
    float4 r;
    float n0 = (v.x - mu) * rstd * g.x + bt.x;  n0 *= sigmoidf_(n0);  r.x = n0 + xv.x;
    float n1 = (v.y - mu) * rstd * g.y + bt.y;  n1 *= sigmoidf_(n1);  r.y = n1 + xv.y;
    float n2 = (v.z - mu) * rstd * g.z + bt.z;  n2 *= sigmoidf_(n2);  r.z = n2 + xv.z;
    float n3 = (v.w - mu) * rstd * g.w + bt.w;  n3 *= sigmoidf_(n3);  r.w = n3 + xv.w;
    ((float4*)out)[idx] = r;
}

// ---------------------------------------------------------------------------
extern "C" void kernel_launch(void* const* d_in, const int* in_sizes, int n_in,
                              void* d_out, int out_size) {
    const float* x         = (const float*)d_in[0];
    const int*   ei        = (const int*)  d_in[1];
    const float* edge_attr = (const float*)d_in[2];
    const float* Wl        = (const float*)d_in[3];
    const float* bl        = (const float*)d_in[4];
    const float* Wr        = (const float*)d_in[5];
    const float* br        = (const float*)d_in[6];
    float* out = (float*)d_out;

    cudaMemcpyToSymbolAsync(cWe,    d_in[7],  1024 * 4, 0, cudaMemcpyDeviceToDevice, 0);
    cudaMemcpyToSymbolAsync(catt,   d_in[8],  64 * 4,   0, cudaMemcpyDeviceToDevice, 0);
    cudaMemcpyToSymbolAsync(cbias,  d_in[9],  64 * 4,   0, cudaMemcpyDeviceToDevice, 0);
    cudaMemcpyToSymbolAsync(cWg1,   d_in[10], 512 * 4,  0, cudaMemcpyDeviceToDevice, 0);
    cudaMemcpyToSymbolAsync(cbg1,   d_in[11], 32 * 4,   0, cudaMemcpyDeviceToDevice, 0);
    cudaMemcpyToSymbolAsync(cWg2,   d_in[12], 32 * 4,   0, cudaMemcpyDeviceToDevice, 0);
    cudaMemcpyToSymbolAsync(cbg2,   d_in[13], 4,        0, cudaMemcpyDeviceToDevice, 0);
    cudaMemcpyToSymbolAsync(cgamma, d_in[14], 64 * 4,   0, cudaMemcpyDeviceToDevice, 0);
    cudaMemcpyToSymbolAsync(cbeta,  d_in[15], 64 * 4,   0, cudaMemcpyDeviceToDevice, 0);

    cudaFuncSetAttribute(k_edge, cudaFuncAttributeMaxDynamicSharedMemorySize,
                         EDGE_SMEM);

    k_prep <<<(NN + 63) / 64, 256>>>(x, Wl, bl, Wr, br, out);
    k_edge <<<EE / ETPB, ETPB, EDGE_SMEM>>>(ei, edge_attr, out);
    k_final<<<NN * 16 / TPB, TPB>>>(x, out);
}

// round 5
// speedup vs baseline: 2.5790x; 1.0313x over previous
#include <cuda_runtime.h>
#include <cuda_fp16.h>

#define NN 100000
#define EE 1600000
#define TPB 256

typedef unsigned long long u64;

// ---- scratch (__device__ globals; no allocations allowed) ----
__device__ float    g_xl [NN * 64];   // x @ Wl + bl  (fp32, message payload)
__device__ __half   g_xlh[NN * 64];   // fp16 copy of xl (logit path)
__device__ __half   g_xrh[NN * 64];   // fp16 x @ Wr + br (logit path only)
__device__ float4   g_denom[NN];      // per-head softmax denominators
__device__ float2   g_gate2[NN];      // {gate_sum, degree} per target

// ---- small params in constant memory ----
__constant__ __align__(16) float cWe[1024];   // [16,64]
__constant__ __align__(16) float cWg1[512];   // [16,32]
__constant__ __align__(16) float cWg2[32];
__constant__ __align__(16) float cbg1[32];
__constant__ __align__(16) float catt[64];
__constant__ __align__(16) float cbias[64];
__constant__ __align__(16) float cgamma[64];
__constant__ __align__(16) float cbeta[64];
__constant__ float cbg2[1];

__device__ __forceinline__ float sigmoidf_(float v) {
    return 1.f / (1.f + __expf(-v));
}
__device__ __forceinline__ u64 pack2(float lo, float hi) {
    u64 r; asm("mov.b64 %0, {%1,%2};" : "=l"(r) : "f"(lo), "f"(hi)); return r;
}
__device__ __forceinline__ void unpack2(u64 v, float& lo, float& hi) {
    asm("mov.b64 {%0,%1}, %2;" : "=f"(lo), "=f"(hi) : "l"(v));
}
__device__ __forceinline__ void fma2(u64& d, u64 a, u64 b) {
    asm("fma.rn.f32x2 %0, %1, %2, %0;" : "+l"(d) : "l"(a), "l"(b));
}
__device__ __forceinline__ void red4(float* p, float a, float b, float c, float d) {
    asm volatile("red.global.add.v4.f32 [%0], {%1,%2,%3,%4};"
                 :: "l"(p), "f"(a), "f"(b), "f"(c), "f"(d) : "memory");
}
__device__ __forceinline__ void red2(float* p, float a, float b) {
    asm volatile("red.global.add.v2.f32 [%0], {%1,%2};"
                 :: "l"(p), "f"(a), "f"(b) : "memory");
}
__device__ __forceinline__ float leaky(float m) { return fmaxf(m, 0.2f * m); }
__device__ __forceinline__ void cpa8(__half* smem_dst, const __half* gsrc) {
    unsigned d = (unsigned)__cvta_generic_to_shared(smem_dst);
    asm volatile("cp.async.ca.shared.global [%0], [%1], 8;"
                 :: "r"(d), "l"(gsrc) : "memory");
}

// ---------------------------------------------------------------------------
// Kernel 1 (round-3 structure, measured 43us): node transforms + inits.
// Emits g_xl (fp32) + g_xlh/g_xrh (fp16). No fp32 xr.
// ---------------------------------------------------------------------------
__global__ void __launch_bounds__(256) k_prep(
        const float* __restrict__ x,
        const float* __restrict__ Wl, const float* __restrict__ bl,
        const float* __restrict__ Wr, const float* __restrict__ br,
        float* __restrict__ out) {
    __shared__ __align__(16) float Ws[64 * 128];   // [k][128 cols: xl|xr]
    __shared__ __align__(16) float xs[64 * 64];    // [node][k]
    int t = threadIdx.x;
    int nb = blockIdx.x * 64;

#pragma unroll
    for (int i = 0; i < 16; i++) {
        int idx = t + i * 256;
        int k = idx >> 6, c = idx & 63;
        Ws[k * 128 + c]      = Wl[idx];
        Ws[k * 128 + 64 + c] = Wr[idx];
    }
#pragma unroll
    for (int i = 0; i < 16; i++) {
        int idx = t + i * 256;
        int n = nb + (idx >> 6);
        bool ok = n < NN;
        xs[idx] = ok ? x[(size_t)n * 64 + (idx & 63)] : 0.f;
        if (ok) out[(size_t)n * 64 + (idx & 63)] = 0.f;
    }
    if (t < 64) {
        int n = nb + t;
        if (n < NN) {
            g_denom[n] = make_float4(0.f, 0.f, 0.f, 0.f);
            g_gate2[n] = make_float2(0.f, 0.f);
        }
    }
    __syncthreads();

    int cg = t & 31, ng = t >> 5;      // warp = one 8-node group (broadcast x)
    int c0 = cg * 4;
    const float* bsrc = (c0 < 64) ? (bl + c0) : (br + (c0 - 64));
    float4 bias = *(const float4*)bsrc;

    u64 acc[8][2];
#pragma unroll
    for (int j = 0; j < 8; j++) {
        acc[j][0] = pack2(bias.x, bias.y);
        acc[j][1] = pack2(bias.z, bias.w);
    }

    for (int k4 = 0; k4 < 16; k4++) {
        float4 xv[8];
#pragma unroll
        for (int j = 0; j < 8; j++)
            xv[j] = *(const float4*)&xs[(ng * 8 + j) * 64 + k4 * 4];
#pragma unroll
        for (int kk = 0; kk < 4; kk++) {
            float4 wv = *(const float4*)&Ws[(k4 * 4 + kk) * 128 + c0];
            u64 w01 = pack2(wv.x, wv.y), w23 = pack2(wv.z, wv.w);
#pragma unroll
            for (int j = 0; j < 8; j++) {
                float xsc = (kk == 0) ? xv[j].x : (kk == 1) ? xv[j].y
                          : (kk == 2) ? xv[j].z : xv[j].w;
                u64 xx = pack2(xsc, xsc);
                fma2(acc[j][0], xx, w01);
                fma2(acc[j][1], xx, w23);
            }
        }
    }

    int cc = c0 & 63;
#pragma unroll
    for (int j = 0; j < 8; j++) {
        int n = nb + ng * 8 + j;
        if (n < NN) {
            float o0, o1, o2, o3;
            unpack2(acc[j][0], o0, o1);
            unpack2(acc[j][1], o2, o3);
            __half2 p01 = __floats2half2_rn(o0, o1);
            __half2 p23 = __floats2half2_rn(o2, o3);
            if (c0 < 64) {
                *(float4*)&g_xl[(size_t)n * 64 + cc] = make_float4(o0, o1, o2, o3);
                *(__half2*)&g_xlh[(size_t)n * 64 + cc]     = p01;
                *(__half2*)&g_xlh[(size_t)n * 64 + cc + 2] = p23;
            } else {
                *(__half2*)&g_xrh[(size_t)n * 64 + cc]     = p01;
                *(__half2*)&g_xrh[(size_t)n * 64 + cc + 2] = p23;
            }
        }
    }
}

// ---------------------------------------------------------------------------
// Kernel 2 (fused edge pass). 128 thr / 4 warps. Per warp (7.2KB):
//   XL,XR: per-head fp16 chunks [2 buf][32 edges][24 halfs] (stride 24 -> no
//          bank conflicts), cp.async double-buffered
//   meta:  [32][8] floats {a0,a1,a2,a3,src,tgt,-,-}
// Phase C gathers fp32 xl rows straight from L2 (2 rows/LDG.128 instr) and
// red4-scatters a*xl -- no full-row smem staging at all.
// ---------------------------------------------------------------------------
#define ETPB 128
#define CH_STRIDE 24                      // halfs per chunk row (16 + 8 pad)
#define CH_BUF    (32 * CH_STRIDE)        // halfs per buffer = 768

__global__ void __launch_bounds__(ETPB, 6) k_edge(
        const int* __restrict__ ei, const float* __restrict__ eag,
        float* __restrict__ out) {
    __shared__ __align__(16) __half sXL[4][2 * CH_BUF];
    __shared__ __align__(16) __half sXR[4][2 * CH_BUF];
    __shared__ __align__(16) float  sMeta[4][32][8];

    int t = threadIdx.x, lane = t & 31, w = t >> 5;
    __half* XL = sXL[w];
    __half* XR = sXR[w];
    float (*meta)[8] = sMeta[w];

    int e = blockIdx.x * ETPB + t;       // EE % ETPB == 0
    int src = ei[e];
    int tgt = ei[EE + e];
    meta[lane][4] = __int_as_float(src);
    meta[lane][5] = __int_as_float(tgt);

    // chunk staging: 8 rows/instr, 4 instr per 32x32B chunk
    int crow = lane >> 2;                // 0..7
    int coff = (lane & 3) * 4;           // halfs (8B per lane)

#define STAGE(h, buf)                                                         \
    {                                                                         \
        _Pragma("unroll")                                                     \
        for (int i_ = 0; i_ < 4; i_++) {                                      \
            int r_  = i_ * 8 + crow;                                          \
            int s_  = __shfl_sync(0xFFFFFFFFu, src, r_);                      \
            int tg_ = __shfl_sync(0xFFFFFFFFu, tgt, r_);                      \
            cpa8(&XL[(buf) * CH_BUF + r_ * CH_STRIDE + coff],                 \
                 g_xlh + (size_t)s_ * 64 + (h) * 16 + coff);                  \
            cpa8(&XR[(buf) * CH_BUF + r_ * CH_STRIDE + coff],                 \
                 g_xrh + (size_t)tg_ * 64 + (h) * 16 + coff);                 \
        }                                                                     \
        asm volatile("cp.async.commit_group;" ::: "memory");                  \
    }

    STAGE(0, 0)
    STAGE(1, 1)

    // ---- overlap: ea load + gate MLP (constants on uniform port) ----
    float ea[16];
    {
        const float4* eap = (const float4*)(eag + (size_t)e * 16);
#pragma unroll
        for (int i = 0; i < 4; i++) {
            float4 v = eap[i];
            ea[4 * i + 0] = v.x; ea[4 * i + 1] = v.y;
            ea[4 * i + 2] = v.z; ea[4 * i + 3] = v.w;
        }
    }
    {
        u64 h2[16];
        const u64* bg1p = (const u64*)cbg1;
#pragma unroll
        for (int j = 0; j < 16; j++) h2[j] = bg1p[j];
        const u64* wg1p = (const u64*)cWg1;
#pragma unroll
        for (int i = 0; i < 16; i++) {
            u64 a2 = pack2(ea[i], ea[i]);
#pragma unroll
            for (int j = 0; j < 16; j++) fma2(h2[j], a2, wg1p[i * 16 + j]);
        }
        float gacc = cbg2[0];
#pragma unroll
        for (int j = 0; j < 16; j++) {
            float h0, h1; unpack2(h2[j], h0, h1);
            gacc += h0 * sigmoidf_(h0) * cWg2[2 * j] +
                    h1 * sigmoidf_(h1) * cWg2[2 * j + 1];
        }
        red2((float*)&g_gate2[tgt], sigmoidf_(gacc), 1.f);
    }

    // ---- phase B: per-head logits (fp16 chunks -> fp32 math) ----
    const u64* we2p = (const u64*)cWe;
    float ah[4];
#pragma unroll
    for (int h = 0; h < 4; h++) {
        if (h < 3) asm volatile("cp.async.wait_group 1;" ::: "memory");
        else       asm volatile("cp.async.wait_group 0;" ::: "memory");
        __syncwarp();

        int b = (h & 1) * CH_BUF + lane * CH_STRIDE;
        uint4 l0 = *(const uint4*)&XL[b];
        uint4 l1 = *(const uint4*)&XL[b + 8];
        uint4 r0 = *(const uint4*)&XR[b];
        uint4 r1 = *(const uint4*)&XR[b + 8];

        u64 s2[8];
        {
            const unsigned* lw = (const unsigned*)&l0;
            const unsigned* rw = (const unsigned*)&r0;
#pragma unroll
            for (int p = 0; p < 4; p++) {
                __half2 sum = __hadd2(*(const __half2*)&lw[p], *(const __half2*)&rw[p]);
                float2 f = __half22float2(sum);
                s2[p] = pack2(f.x, f.y);
            }
            lw = (const unsigned*)&l1;
            rw = (const unsigned*)&r1;
#pragma unroll
            for (int p = 0; p < 4; p++) {
                __half2 sum = __hadd2(*(const __half2*)&lw[p], *(const __half2*)&rw[p]);
                float2 f = __half22float2(sum);
                s2[4 + p] = pack2(f.x, f.y);
            }
        }
#pragma unroll
        for (int i = 0; i < 16; i++) {
            u64 a2 = pack2(ea[i], ea[i]);
#pragma unroll
            for (int p = 0; p < 8; p++)
                fma2(s2[p], a2, we2p[i * 32 + h * 8 + p]);
        }
        float acc = 0.f;
#pragma unroll
        for (int p = 0; p < 8; p++) {
            float m0, m1; unpack2(s2[p], m0, m1);
            acc += leaky(m0) * catt[h * 16 + 2 * p] +
                   leaky(m1) * catt[h * 16 + 2 * p + 1];
        }
        ah[h] = __expf(acc);   // no max-shift: ratios invariant, range safe
        __syncwarp();
        if (h < 2) STAGE(h + 2, h & 1)
    }
#undef STAGE

    *(float4*)&meta[lane][0] = make_float4(ah[0], ah[1], ah[2], ah[3]);
    red4((float*)&g_denom[tgt], ah[0], ah[1], ah[2], ah[3]);
    __syncwarp();

    // ---- phase C: cooperative gather (L2) + red4 scatter of a*xl ----
    int cofs = (lane & 15) * 4;          // 16 lanes cover a 256B row
    int rsel = lane >> 4;                // 2 rows per instruction
    int h_c  = (lane >> 2) & 3;          // head owning this 16B chunk
#pragma unroll
    for (int i = 0; i < 16; i++) {
        int r  = 2 * i + rsel;
        float a = meta[r][h_c];
        int s  = __float_as_int(meta[r][4]);
        int tg = __float_as_int(meta[r][5]);
        float4 v = *(const float4*)&g_xl[(size_t)s * 64 + cofs];
        red4(out + (size_t)tg * 64 + cofs, v.x * a, v.y * a, v.z * a, v.w * a);
    }
}

// ---------------------------------------------------------------------------
// Kernel 3: node epilogue — 16 threads/node, float4 lanes, constant params.
// ---------------------------------------------------------------------------
__global__ void k_final(const float* __restrict__ x, float* __restrict__ out) {
    int gid = blockIdx.x * blockDim.x + threadIdx.x;
    int n = gid >> 4;
    int q = threadIdx.x & 15;
    int h = q >> 2;

    float2 gd = g_gate2[n];
    float mg = gd.x / fmaxf(gd.y, 1.f);
    float4 den4 = g_denom[n];
    float den = (h == 0) ? den4.x : (h == 1) ? den4.y : (h == 2) ? den4.z : den4.w;
    float inv = den > 0.f ? 1.f / den : 0.f;

    size_t idx = (size_t)n * 16 + q;
    float4 o  = ((const float4*)out)[idx];
    float4 cb = ((const float4*)cbias)[q];
    float4 v;
    v.x = (o.x * inv + cb.x) * mg;
    v.y = (o.y * inv + cb.y) * mg;
    v.z = (o.z * inv + cb.z) * mg;
    v.w = (o.w * inv + cb.w) * mg;

    float s  = v.x + v.y + v.z + v.w;
    float sq = v.x * v.x + v.y * v.y + v.z * v.z + v.w * v.w;
#pragma unroll
    for (int ofs = 1; ofs < 16; ofs <<= 1) {
        s  += __shfl_xor_sync(0xFFFFFFFFu, s,  ofs);
        sq += __shfl_xor_sync(0xFFFFFFFFu, sq, ofs);
    }
    float mu   = s * (1.f / 64.f);
    float var  = sq * (1.f / 64.f) - mu * mu;
    float rstd = rsqrtf(var + 1e-5f);

    float4 g  = ((const float4*)cgamma)[q];
    float4 bt = ((const float4*)cbeta)[q];
    float4 xv = ((const float4*)x)[idx];
    float4 r;
    float n0 = (v.x - mu) * rstd * g.x + bt.x;  n0 *= sigmoidf_(n0);  r.x = n0 + xv.x;
    float n1 = (v.y - mu) * rstd * g.y + bt.y;  n1 *= sigmoidf_(n1);  r.y = n1 + xv.y;
    float n2 = (v.z - mu) * rstd * g.z + bt.z;  n2 *= sigmoidf_(n2);  r.z = n2 + xv.z;
    float n3 = (v.w - mu) * rstd * g.w + bt.w;  n3 *= sigmoidf_(n3);  r.w = n3 + xv.w;
    ((float4*)out)[idx] = r;
}

// ---------------------------------------------------------------------------
extern "C" void kernel_launch(void* const* d_in, const int* in_sizes, int n_in,
                              void* d_out, int out_size) {
    const float* x         = (const float*)d_in[0];
    const int*   ei        = (const int*)  d_in[1];
    const float* edge_attr = (const float*)d_in[2];
    const float* Wl        = (const float*)d_in[3];
    const float* bl        = (const float*)d_in[4];
    const float* Wr        = (const float*)d_in[5];
    const float* br        = (const float*)d_in[6];
    float* out = (float*)d_out;

    cudaMemcpyToSymbolAsync(cWe,    d_in[7],  1024 * 4, 0, cudaMemcpyDeviceToDevice, 0);
    cudaMemcpyToSymbolAsync(catt,   d_in[8],  64 * 4,   0, cudaMemcpyDeviceToDevice, 0);
    cudaMemcpyToSymbolAsync(cbias,  d_in[9],  64 * 4,   0, cudaMemcpyDeviceToDevice, 0);
    cudaMemcpyToSymbolAsync(cWg1,   d_in[10], 512 * 4,  0, cudaMemcpyDeviceToDevice, 0);
    cudaMemcpyToSymbolAsync(cbg1,   d_in[11], 32 * 4,   0, cudaMemcpyDeviceToDevice, 0);
    cudaMemcpyToSymbolAsync(cWg2,   d_in[12], 32 * 4,   0, cudaMemcpyDeviceToDevice, 0);
    cudaMemcpyToSymbolAsync(cbg2,   d_in[13], 4,        0, cudaMemcpyDeviceToDevice, 0);
    cudaMemcpyToSymbolAsync(cgamma, d_in[14], 64 * 4,   0, cudaMemcpyDeviceToDevice, 0);
    cudaMemcpyToSymbolAsync(cbeta,  d_in[15], 64 * 4,   0, cudaMemcpyDeviceToDevice, 0);

    k_prep <<<(NN + 63) / 64, 256>>>(x, Wl, bl, Wr, br, out);
    k_edge <<<EE / ETPB, ETPB>>>(ei, edge_attr, out);
    k_final<<<NN * 16 / TPB, TPB>>>(x, out);
}

// round 7
// speedup vs baseline: 3.1248x; 1.2116x over previous
#include <cuda_runtime.h>
#include <cuda_fp16.h>

#define NN 100000
#define EE 1600000
#define TPB 256

typedef unsigned long long u64;

// ---- scratch (__device__ globals; no allocations allowed) ----
__device__ __half   g_xlh[NN * 64];   // fp16 x @ Wl + bl (logits + messages)
__device__ __half   g_xrh[NN * 64];   // fp16 x @ Wr + br (logits only)
__device__ float4   g_denom[NN];      // per-head softmax denominators
__device__ float2   g_gate2[NN];      // {gate_sum, degree} per target

// ---- small params in constant memory ----
__constant__ __align__(16) float cWe[1024];   // [16,64]
__constant__ __align__(16) float cWg1[512];   // [16,32]
__constant__ __align__(16) float cWg2[32];
__constant__ __align__(16) float cbg1[32];
__constant__ __align__(16) float catt[64];
__constant__ __align__(16) float cbias[64];
__constant__ __align__(16) float cgamma[64];
__constant__ __align__(16) float cbeta[64];
__constant__ float cbg2[1];

__device__ __forceinline__ float sigmoidf_(float v) {
    return 1.f / (1.f + __expf(-v));
}
__device__ __forceinline__ u64 pack2(float lo, float hi) {
    u64 r; asm("mov.b64 %0, {%1,%2};" : "=l"(r) : "f"(lo), "f"(hi)); return r;
}
__device__ __forceinline__ void unpack2(u64 v, float& lo, float& hi) {
    asm("mov.b64 {%0,%1}, %2;" : "=f"(lo), "=f"(hi) : "l"(v));
}
__device__ __forceinline__ void fma2(u64& d, u64 a, u64 b) {
    asm("fma.rn.f32x2 %0, %1, %2, %0;" : "+l"(d) : "l"(a), "l"(b));
}
__device__ __forceinline__ void red4(float* p, float a, float b, float c, float d) {
    asm volatile("red.global.add.v4.f32 [%0], {%1,%2,%3,%4};"
                 :: "l"(p), "f"(a), "f"(b), "f"(c), "f"(d) : "memory");
}
__device__ __forceinline__ void red2(float* p, float a, float b) {
    asm volatile("red.global.add.v2.f32 [%0], {%1,%2};"
                 :: "l"(p), "f"(a), "f"(b) : "memory");
}
__device__ __forceinline__ float leaky(float m) { return fmaxf(m, 0.2f * m); }
__device__ __forceinline__ void cpa16(__half* smem_dst, const __half* gsrc) {
    unsigned d = (unsigned)__cvta_generic_to_shared(smem_dst);
    asm volatile("cp.async.ca.shared.global [%0], [%1], 16;"
                 :: "r"(d), "l"(gsrc) : "memory");
}
__device__ __forceinline__ unsigned h2_bits(__half2 v) {
    unsigned r;
    asm("mov.b32 %0, %1;" : "=r"(r) : "r"(*reinterpret_cast<unsigned*>(&v)));
    return r;
}

// ---------------------------------------------------------------------------
// Kernel 1: node transforms + inits. Emits fp16 g_xlh / g_xrh only.
// ---------------------------------------------------------------------------
__global__ void __launch_bounds__(256) k_prep(
        const float* __restrict__ x,
        const float* __restrict__ Wl, const float* __restrict__ bl,
        const float* __restrict__ Wr, const float* __restrict__ br,
        float* __restrict__ out) {
    __shared__ __align__(16) float Ws[64 * 128];   // [k][128 cols: xl|xr]
    __shared__ __align__(16) float xs[64 * 64];    // [node][k]
    int t = threadIdx.x;
    int nb = blockIdx.x * 64;

#pragma unroll
    for (int i = 0; i < 16; i++) {
        int idx = t + i * 256;
        int k = idx >> 6, c = idx & 63;
        Ws[k * 128 + c]      = Wl[idx];
        Ws[k * 128 + 64 + c] = Wr[idx];
    }
#pragma unroll
    for (int i = 0; i < 16; i++) {
        int idx = t + i * 256;
        int n = nb + (idx >> 6);
        bool ok = n < NN;
        xs[idx] = ok ? x[(size_t)n * 64 + (idx & 63)] : 0.f;
        if (ok) out[(size_t)n * 64 + (idx & 63)] = 0.f;
    }
    if (t < 64) {
        int n = nb + t;
        if (n < NN) {
            g_denom[n] = make_float4(0.f, 0.f, 0.f, 0.f);
            g_gate2[n] = make_float2(0.f, 0.f);
        }
    }
    __syncthreads();

    int cg = t & 31, ng = t >> 5;      // warp = one 8-node group (broadcast x)
    int c0 = cg * 4;
    const float* bsrc = (c0 < 64) ? (bl + c0) : (br + (c0 - 64));
    float4 bias = *(const float4*)bsrc;

    u64 acc[8][2];
#pragma unroll
    for (int j = 0; j < 8; j++) {
        acc[j][0] = pack2(bias.x, bias.y);
        acc[j][1] = pack2(bias.z, bias.w);
    }

    for (int k4 = 0; k4 < 16; k4++) {
        float4 xv[8];
#pragma unroll
        for (int j = 0; j < 8; j++)
            xv[j] = *(const float4*)&xs[(ng * 8 + j) * 64 + k4 * 4];
#pragma unroll
        for (int kk = 0; kk < 4; kk++) {
            float4 wv = *(const float4*)&Ws[(k4 * 4 + kk) * 128 + c0];
            u64 w01 = pack2(wv.x, wv.y), w23 = pack2(wv.z, wv.w);
#pragma unroll
            for (int j = 0; j < 8; j++) {
                float xsc = (kk == 0) ? xv[j].x : (kk == 1) ? xv[j].y
                          : (kk == 2) ? xv[j].z : xv[j].w;
                u64 xx = pack2(xsc, xsc);
                fma2(acc[j][0], xx, w01);
                fma2(acc[j][1], xx, w23);
            }
        }
    }

    __half* dsth = (c0 < 64) ? g_xlh : g_xrh;
    int cc = c0 & 63;
#pragma unroll
    for (int j = 0; j < 8; j++) {
        int n = nb + ng * 8 + j;
        if (n < NN) {
            float o0, o1, o2, o3;
            unpack2(acc[j][0], o0, o1);
            unpack2(acc[j][1], o2, o3);
            uint2 p;
            p.x = h2_bits(__floats2half2_rn(o0, o1));
            p.y = h2_bits(__floats2half2_rn(o2, o3));
            *(uint2*)&dsth[(size_t)n * 64 + cc] = p;
        }
    }
}

// ---------------------------------------------------------------------------
// Kernel 2 (fused edge pass). 128 thr / 4 warps. Per warp (10KB smem):
//   XL, XR: full fp16 rows [32 edges][72 halfs] (144B stride, conflict-free,
//           16B cp.async units -> 4 full 128B rows per instruction, 1 wf/row)
//   meta:   [32][8] {a0,a1,a2,a3,tgt,...}
// Phase C builds messages from the SAME staged fp16 xl rows (no L2 regather).
// ---------------------------------------------------------------------------
#define ETPB 128
#define RST 72                              // halfs per staged row (64 + 8 pad)

__global__ void __launch_bounds__(ETPB, 5) k_edge(
        const int* __restrict__ ei, const float* __restrict__ eag,
        float* __restrict__ out) {
    __shared__ __align__(16) __half sXL[4][32 * RST];
    __shared__ __align__(16) __half sXR[4][32 * RST];
    __shared__ __align__(16) float  sMeta[4][32][8];

    int t = threadIdx.x, lane = t & 31, w = t >> 5;
    __half* XL = sXL[w];
    __half* XR = sXR[w];
    float (*meta)[8] = sMeta[w];

    int e = blockIdx.x * ETPB + t;          // EE % ETPB == 0
    int src = ei[e];
    int tgt = ei[EE + e];

    // ---- phase A: stage full fp16 rows (4 rows / 1 line each per instr) ----
    int rlane = lane >> 3;                  // 4 rows per instruction
    int off8  = (lane & 7) * 8;             // 8 lanes x 16B cover one 128B row
#pragma unroll
    for (int i = 0; i < 8; i++) {
        int r  = i * 4 + rlane;
        int s  = __shfl_sync(0xFFFFFFFFu, src, r);
        int tg = __shfl_sync(0xFFFFFFFFu, tgt, r);
        cpa16(&XL[r * RST + off8], g_xlh + (size_t)s  * 64 + off8);
        cpa16(&XR[r * RST + off8], g_xrh + (size_t)tg * 64 + off8);
    }
    asm volatile("cp.async.commit_group;" ::: "memory");

    // ---- overlap: ea load + gate MLP (constants on uniform port) ----
    float ea[16];
    {
        const float4* eap = (const float4*)(eag + (size_t)e * 16);
#pragma unroll
        for (int i = 0; i < 4; i++) {
            float4 v = eap[i];
            ea[4 * i + 0] = v.x; ea[4 * i + 1] = v.y;
            ea[4 * i + 2] = v.z; ea[4 * i + 3] = v.w;
        }
    }
    {
        u64 h2[16];
        const u64* bg1p = (const u64*)cbg1;
#pragma unroll
        for (int j = 0; j < 16; j++) h2[j] = bg1p[j];
        const u64* wg1p = (const u64*)cWg1;
#pragma unroll
        for (int i = 0; i < 16; i++) {
            u64 a2 = pack2(ea[i], ea[i]);
#pragma unroll
            for (int j = 0; j < 16; j++) fma2(h2[j], a2, wg1p[i * 16 + j]);
        }
        float gacc = cbg2[0];
#pragma unroll
        for (int j = 0; j < 16; j++) {
            float h0, h1; unpack2(h2[j], h0, h1);
            gacc += h0 * sigmoidf_(h0) * cWg2[2 * j] +
                    h1 * sigmoidf_(h1) * cWg2[2 * j + 1];
        }
        red2((float*)&g_gate2[tgt], sigmoidf_(gacc), 1.f);
    }

    asm volatile("cp.async.wait_group 0;" ::: "memory");
    __syncwarp();

    // ---- phase B: per-head logits from staged fp16 rows ----
    const u64* we2p = (const u64*)cWe;
    float ah[4];
#pragma unroll
    for (int h = 0; h < 4; h++) {
        uint4 l0 = *(const uint4*)&XL[lane * RST + h * 16];
        uint4 l1 = *(const uint4*)&XL[lane * RST + h * 16 + 8];
        uint4 r0 = *(const uint4*)&XR[lane * RST + h * 16];
        uint4 r1 = *(const uint4*)&XR[lane * RST + h * 16 + 8];

        u64 s2[8];
        {
            const unsigned* lw = (const unsigned*)&l0;
            const unsigned* rw = (const unsigned*)&r0;
#pragma unroll
            for (int p = 0; p < 4; p++) {
                __half2 sum = __hadd2(*(const __half2*)&lw[p], *(const __half2*)&rw[p]);
                float2 f = __half22float2(sum);
                s2[p] = pack2(f.x, f.y);
            }
            lw = (const unsigned*)&l1;
            rw = (const unsigned*)&r1;
#pragma unroll
            for (int p = 0; p < 4; p++) {
                __half2 sum = __hadd2(*(const __half2*)&lw[p], *(const __half2*)&rw[p]);
                float2 f = __half22float2(sum);
                s2[4 + p] = pack2(f.x, f.y);
            }
        }
#pragma unroll
        for (int i = 0; i < 16; i++) {
            u64 a2 = pack2(ea[i], ea[i]);
#pragma unroll
            for (int p = 0; p < 8; p++)
                fma2(s2[p], a2, we2p[i * 32 + h * 8 + p]);
        }
        float acc = 0.f;
#pragma unroll
        for (int p = 0; p < 8; p++) {
            float m0, m1; unpack2(s2[p], m0, m1);
            acc += leaky(m0) * catt[h * 16 + 2 * p] +
                   leaky(m1) * catt[h * 16 + 2 * p + 1];
        }
        ah[h] = __expf(acc);   // no max-shift: ratios invariant, range safe
    }

    *(float4*)&meta[lane][0] = make_float4(ah[0], ah[1], ah[2], ah[3]);
    meta[lane][4] = __int_as_float(tgt);
    red4((float*)&g_denom[tgt], ah[0], ah[1], ah[2], ah[3]);
    __syncwarp();

    // ---- phase C: messages from staged fp16 xl, red4 scatter (fp32) ----
    int q    = lane & 15;                 // 16 lanes cover a 64-float out row
    int rsel = lane >> 4;                 // 2 rows per iteration
    int h_c  = q >> 2;                    // head owning this 16B out chunk
#pragma unroll
    for (int i = 0; i < 16; i++) {
        int r   = 2 * i + rsel;
        float a = meta[r][h_c];
        int tg  = __float_as_int(meta[r][4]);
        uint2 hv = *(const uint2*)&XL[r * RST + q * 4];
        float2 f01 = __half22float2(*(const __half2*)&hv.x);
        float2 f23 = __half22float2(*(const __half2*)&hv.y);
        red4(out + (size_t)tg * 64 + q * 4,
             f01.x * a, f01.y * a, f23.x * a, f23.y * a);
    }
}

// ---------------------------------------------------------------------------
// Kernel 3: node epilogue — 16 threads/node, float4 lanes, constant params.
// ---------------------------------------------------------------------------
__global__ void k_final(const float* __restrict__ x, float* __restrict__ out) {
    int gid = blockIdx.x * blockDim.x + threadIdx.x;
    int n = gid >> 4;
    int q = threadIdx.x & 15;
    int h = q >> 2;

    float2 gd = g_gate2[n];
    float mg = gd.x / fmaxf(gd.y, 1.f);
    float4 den4 = g_denom[n];
    float den = (h == 0) ? den4.x : (h == 1) ? den4.y : (h == 2) ? den4.z : den4.w;
    float inv = den > 0.f ? 1.f / den : 0.f;

    size_t idx = (size_t)n * 16 + q;
    float4 o  = ((const float4*)out)[idx];
    float4 cb = ((const float4*)cbias)[q];
    float4 v;
    v.x = (o.x * inv + cb.x) * mg;
    v.y = (o.y * inv + cb.y) * mg;
    v.z = (o.z * inv + cb.z) * mg;
    v.w = (o.w * inv + cb.w) * mg;

    float s  = v.x + v.y + v.z + v.w;
    float sq = v.x * v.x + v.y * v.y + v.z * v.z + v.w * v.w;
#pragma unroll
    for (int ofs = 1; ofs < 16; ofs <<= 1) {
        s  += __shfl_xor_sync(0xFFFFFFFFu, s,  ofs);
        sq += __shfl_xor_sync(0xFFFFFFFFu, sq, ofs);
    }
    float mu   = s * (1.f / 64.f);
    float var  = sq * (1.f / 64.f) - mu * mu;
    float rstd = rsqrtf(var + 1e-5f);

    float4 g  = ((const float4*)cgamma)[q];
    float4 bt = ((const float4*)cbeta)[q];
    float4 xv = ((const float4*)x)[idx];
    float4 r;
    float n0 = (v.x - mu) * rstd * g.x + bt.x;  n0 *= sigmoidf_(n0);  r.x = n0 + xv.x;
    float n1 = (v.y - mu) * rstd * g.y + bt.y;  n1 *= sigmoidf_(n1);  r.y = n1 + xv.y;
    float n2 = (v.z - mu) * rstd * g.z + bt.z;  n2 *= sigmoidf_(n2);  r.z = n2 + xv.z;
    float n3 = (v.w - mu) * rstd * g.w + bt.w;  n3 *= sigmoidf_(n3);  r.w = n3 + xv.w;
    ((float4*)out)[idx] = r;
}

// ---------------------------------------------------------------------------
extern "C" void kernel_launch(void* const* d_in, const int* in_sizes, int n_in,
                              void* d_out, int out_size) {
    const float* x         = (const float*)d_in[0];
    const int*   ei        = (const int*)  d_in[1];
    const float* edge_attr = (const float*)d_in[2];
    const float* Wl        = (const float*)d_in[3];
    const float* bl        = (const float*)d_in[4];
    const float* Wr        = (const float*)d_in[5];
    const float* br        = (const float*)d_in[6];
    float* out = (float*)d_out;

    cudaMemcpyToSymbolAsync(cWe,    d_in[7],  1024 * 4, 0, cudaMemcpyDeviceToDevice, 0);
    cudaMemcpyToSymbolAsync(catt,   d_in[8],  64 * 4,   0, cudaMemcpyDeviceToDevice, 0);
    cudaMemcpyToSymbolAsync(cbias,  d_in[9],  64 * 4,   0, cudaMemcpyDeviceToDevice, 0);
    cudaMemcpyToSymbolAsync(cWg1,   d_in[10], 512 * 4,  0, cudaMemcpyDeviceToDevice, 0);
    cudaMemcpyToSymbolAsync(cbg1,   d_in[11], 32 * 4,   0, cudaMemcpyDeviceToDevice, 0);
    cudaMemcpyToSymbolAsync(cWg2,   d_in[12], 32 * 4,   0, cudaMemcpyDeviceToDevice, 0);
    cudaMemcpyToSymbolAsync(cbg2,   d_in[13], 4,        0, cudaMemcpyDeviceToDevice, 0);
    cudaMemcpyToSymbolAsync(cgamma, d_in[14], 64 * 4,   0, cudaMemcpyDeviceToDevice, 0);
    cudaMemcpyToSymbolAsync(cbeta,  d_in[15], 64 * 4,   0, cudaMemcpyDeviceToDevice, 0);

    k_prep <<<(NN + 63) / 64, 256>>>(x, Wl, bl, Wr, br, out);
    k_edge <<<EE / ETPB, ETPB>>>(ei, edge_attr, out);
    k_final<<<NN * 16 / TPB, TPB>>>(x, out);
}